// round 16
// baseline (speedup 1.0000x reference)
#include <cuda_runtime.h>
#include <math.h>
#include <stdint.h>

#define NB 4
#define NH 48
#define NW 48
#define NDM 192
#define NDI 384
#define NK 4
#define NL 2304
#define NDS 16
#define NDTR 12
#define NCC 44                 // DTR + 2*DS
#define NBL (NB*NL)            // 9216
#define NBKL (NB*NK*NL)        // 36864

// ---------------- scratch (static device memory; no allocations) ----------------
__device__ float g_xz[NBL * 2 * NDI];
__device__ float g_xc[NBL * NDI];            // aliased: becomes g_y after interp
__device__ float g_xtc[NBL * NDI];
__device__ float g_xs[NB * NK * NL * NDI];
__device__ float g_dbl[NBKL * NCC];
__device__ float g_delta[NB * NK * NL * NDI];
__device__ float g_outy[NB * NK * NL * NDI];

__device__ __forceinline__ float silu_f(float x) { return x / (1.f + __expf(-x)); }
__device__ __forceinline__ float mm2(float a, float b) { return 0.5f * (a + b) + fmaxf(a, b); }

// ---- packed fp32x2 helpers ----
__device__ __forceinline__ uint64_t pack2(float lo, float hi) {
    uint64_t r; asm("mov.b64 %0, {%1, %2};" : "=l"(r) : "f"(lo), "f"(hi)); return r;
}
__device__ __forceinline__ void unpack2(uint64_t v, float& lo, float& hi) {
    asm("mov.b64 {%0, %1}, %2;" : "=f"(lo), "=f"(hi) : "l"(v));
}
__device__ __forceinline__ void ffma2(uint64_t& d, uint64_t a, uint64_t b) {
    asm("fma.rn.f32x2 %0, %1, %2, %0;" : "+l"(d) : "l"(a), "l"(b));
}

// ---------------- generic SGEMM body: C[M,N] = A[M,K] * B[N,K]^T ----------------
// BM=128, BN=64, BK=16, 256 threads, 8x4 per-thread tile. Register-prefetch
// double buffering. R16: Bs stored DUPLICATED ({b,b} pairs) so both FFMA2
// operands come straight from LDS.64 — no pack MOVs in the inner loop.
__device__ __forceinline__ void sgemm_body(const float* __restrict__ A,
                                           const float* __restrict__ B,
                                           float* __restrict__ C,
                                           int M, int N, int K)
{
    __shared__ float As[16][132];
    __shared__ float Bsd[16][136];   // duplicated: Bsd[kk][2c] = Bsd[kk][2c+1] = b
    const int tid = threadIdx.x;
    const int row0 = blockIdx.y * 128;
    const int col0 = blockIdx.x * 64;
    const int tx = tid & 15;
    const int ty = tid >> 4;
    const int lr = tid >> 2;
    const int lc = (tid & 3) << 2;

    const float* Ap0 = A + (size_t)(row0 + lr) * K + lc;
    const float* Ap1 = A + (size_t)(row0 + lr + 64) * K + lc;
    const float* Bp0 = B + (size_t)(col0 + lr) * K + lc;

    uint64_t acc2[4][4];
#pragma unroll
    for (int i = 0; i < 4; i++)
#pragma unroll
        for (int j = 0; j < 4; j++) acc2[i][j] = 0ull;

    float4 a0 = *(const float4*)(Ap0);
    float4 a1 = *(const float4*)(Ap1);
    float4 b0 = *(const float4*)(Bp0);

    for (int k0 = 0; k0 < K; k0 += 16) {
        As[lc + 0][lr] = a0.x; As[lc + 1][lr] = a0.y; As[lc + 2][lr] = a0.z; As[lc + 3][lr] = a0.w;
        As[lc + 0][lr + 64] = a1.x; As[lc + 1][lr + 64] = a1.y; As[lc + 2][lr + 64] = a1.z; As[lc + 3][lr + 64] = a1.w;
        // duplicated store: one STS.64 of {b,b} per k-row
        *(uint64_t*)&Bsd[lc + 0][2 * lr] = pack2(b0.x, b0.x);
        *(uint64_t*)&Bsd[lc + 1][2 * lr] = pack2(b0.y, b0.y);
        *(uint64_t*)&Bsd[lc + 2][2 * lr] = pack2(b0.z, b0.z);
        *(uint64_t*)&Bsd[lc + 3][2 * lr] = pack2(b0.w, b0.w);
        __syncthreads();
        if (k0 + 16 < K) {
            a0 = *(const float4*)(Ap0 + k0 + 16);
            a1 = *(const float4*)(Ap1 + k0 + 16);
            b0 = *(const float4*)(Bp0 + k0 + 16);
        }
#pragma unroll
        for (int kk = 0; kk < 16; kk++) {
            uint64_t ap[4], bd[4];
#pragma unroll
            for (int ip = 0; ip < 4; ip++)
                ap[ip] = *(const uint64_t*)&As[kk][ty * 8 + 2 * ip];     // LDS.64
#pragma unroll
            for (int j = 0; j < 4; j++)
                bd[j] = *(const uint64_t*)&Bsd[kk][2 * (tx * 4 + j)];    // LDS.64 {b,b}
#pragma unroll
            for (int ip = 0; ip < 4; ip++)
#pragma unroll
                for (int j = 0; j < 4; j++) ffma2(acc2[ip][j], ap[ip], bd[j]);
        }
        __syncthreads();
    }
#pragma unroll
    for (int ip = 0; ip < 4; ip++) {
        float lo[4], hi[4];
#pragma unroll
        for (int j = 0; j < 4; j++) unpack2(acc2[ip][j], lo[j], hi[j]);
        *(float4*)(C + (size_t)(row0 + ty * 8 + 2 * ip) * N + col0 + tx * 4) =
            make_float4(lo[0], lo[1], lo[2], lo[3]);
        *(float4*)(C + (size_t)(row0 + ty * 8 + 2 * ip + 1) * N + col0 + tx * 4) =
            make_float4(hi[0], hi[1], hi[2], hi[3]);
    }
}

__global__ __launch_bounds__(256) void gemm_inproj(const float* __restrict__ x,
                                                   const float* __restrict__ w)
{
    sgemm_body(x, w, g_xz, NBL, 2 * NDI, NDM);
}

__global__ __launch_bounds__(256) void gemm_outproj(const float* __restrict__ w,
                                                    float* __restrict__ out)
{
    sgemm_body(g_xc /* holds y after combine */, w, out, NBL, NDM, NDI);
}

// ---------------- depthwise conv on xin (from g_xz cols 0..383) + SiLU ----------------
__global__ void conv_xc_kernel(const float* __restrict__ wgt, const float* __restrict__ bias)
{
    int idx = blockIdx.x * blockDim.x + threadIdx.x;
    if (idx >= NBL * NDI) return;
    int c = idx % NDI;
    int pix = idx / NDI;
    int w = pix % NW;
    int h = (pix / NW) % NH;
    int b = pix / (NW * NH);
    float s = __ldg(bias + c);
#pragma unroll
    for (int dy = -1; dy <= 1; dy++) {
        int hh = h + dy;
        if (hh < 0 || hh >= NH) continue;
#pragma unroll
        for (int dx = -1; dx <= 1; dx++) {
            int ww = w + dx;
            if (ww < 0 || ww >= NW) continue;
            s = fmaf(g_xz[(size_t)(b * NL + hh * NW + ww) * (2 * NDI) + c],
                     __ldg(wgt + c * 9 + (dy + 1) * 3 + (dx + 1)), s);
        }
    }
    g_xc[(size_t)pix * NDI + c] = silu_f(s);
}

// ---------------- grouped conv on xt (192 in ch -> 384 out ch, ic = oc>>1) + SiLU ----------------
__global__ void conv_xt_kernel(const float* __restrict__ xt,
                               const float* __restrict__ wgt, const float* __restrict__ bias)
{
    int idx = blockIdx.x * blockDim.x + threadIdx.x;
    if (idx >= NBL * NDI) return;
    int c = idx % NDI;
    int pix = idx / NDI;
    int w = pix % NW;
    int h = (pix / NW) % NH;
    int b = pix / (NW * NH);
    int ic = c >> 1;
    float s = __ldg(bias + c);
#pragma unroll
    for (int dy = -1; dy <= 1; dy++) {
        int hh = h + dy;
        if (hh < 0 || hh >= NH) continue;
#pragma unroll
        for (int dx = -1; dx <= 1; dx++) {
            int ww = w + dx;
            if (ww < 0 || ww >= NW) continue;
            s = fmaf(__ldg(xt + (size_t)(b * NL + hh * NW + ww) * NDM + ic),
                     __ldg(wgt + c * 9 + (dy + 1) * 3 + (dx + 1)), s);
        }
    }
    g_xtc[(size_t)pix * NDI + c] = silu_f(s);
}

// ---------------- interpolate: build 4 directional sequences xs[b,k,l,d] ----------------
__global__ void interp_kernel()
{
    int idx = blockIdx.x * blockDim.x + threadIdx.x;
    if (idx >= NBL * NDI) return;
    int d = idx % NDI;
    int pix = idx / NDI;
    int w = pix % NW;
    int h = (pix / NW) % NH;
    int b = pix / (NW * NH);
    const float* XC = g_xc + (size_t)b * NL * NDI + d;
    const float* XT = g_xtc + (size_t)b * NL * NDI + d;

    float a0, a1;
    if ((h & 1) == 0) { a0 = XC[(h * NW + w) * NDI]; a1 = XC[((h + 1) * NW + w) * NDI]; }
    else              { a0 = XT[((h - 1) * NW + w) * NDI]; a1 = XT[(h * NW + w) * NDI]; }
    float vrow = mm2(a0, a1);
    if ((w & 1) == 0) { a0 = XC[(h * NW + w) * NDI]; a1 = XC[(h * NW + w + 1) * NDI]; }
    else              { a0 = XT[(h * NW + w - 1) * NDI]; a1 = XT[(h * NW + w) * NDI]; }
    float vcol = mm2(a0, a1);

    float* XS = g_xs + (size_t)b * NK * NL * NDI + d;
    int l0 = w * NH + h;
    XS[(size_t)(0 * NL + l0) * NDI] = vrow;
    XS[(size_t)(1 * NL + (w * NH + (NH - 1 - h))) * NDI] = vrow;
    int l2 = h * NW + w;
    XS[(size_t)(2 * NL + l2) * NDI] = vcol;
    XS[(size_t)(3 * NL + (h * NW + (NW - 1 - w))) * NDI] = vcol;
}

// ---------------- x_dbl: [44] = W_k[44,384] @ xs[b,k,l,:] ----------------
// R16: w-pairs loaded directly as uint64 (LDS.64) — removes 22 pack MOVs per kk.
__global__ __launch_bounds__(128) void xdbl_kernel(const float* __restrict__ Wp)
{
    __shared__ float xsm[256][33];
    __shared__ float ws2[32][48];
    const int kdir = blockIdx.y;
    const int row0 = blockIdx.x * 256;
    const int b = row0 / NL;
    const int l0 = row0 % NL;
    const float* xbase = g_xs + ((size_t)(b * NK + kdir) * NL + l0) * NDI;
    const int tid = threadIdx.x;

    uint64_t accA2[22], accB2[22];
#pragma unroll
    for (int c = 0; c < 22; c++) { accA2[c] = 0ull; accB2[c] = 0ull; }

    for (int dk0 = 0; dk0 < NDI; dk0 += 32) {
#pragma unroll
        for (int p = 0; p < 16; p++) {
            int lin = p * 128 + tid;
            int r = lin >> 3;
            int cc = (lin & 7) << 2;
            float4 v = *(const float4*)(xbase + (size_t)r * NDI + dk0 + cc);
            xsm[r][cc] = v.x; xsm[r][cc + 1] = v.y; xsm[r][cc + 2] = v.z; xsm[r][cc + 3] = v.w;
        }
        for (int p = tid; p < NCC * 32; p += 128) {
            int c = p >> 5, dd = p & 31;
            ws2[dd][c] = Wp[((size_t)kdir * NCC + c) * NDI + dk0 + dd];
        }
        __syncthreads();
        for (int kk = 0; kk < 32; kk++) {
            float xa = xsm[tid][kk];
            float xb = xsm[tid + 128][kk];
            uint64_t xad = pack2(xa, xa);
            uint64_t xbd = pack2(xb, xb);
            const uint64_t* wrow = (const uint64_t*)&ws2[kk][0];  // 192B stride, 8B aligned
#pragma unroll
            for (int cp = 0; cp < 22; cp++) {
                uint64_t wp2 = wrow[cp];                          // LDS.64
                ffma2(accA2[cp], xad, wp2);
                ffma2(accB2[cp], xbd, wp2);
            }
        }
        __syncthreads();
    }
    float* outA = g_dbl + ((size_t)(b * NK + kdir) * NL + l0 + tid) * NCC;
    float* outB = outA + (size_t)128 * NCC;
#pragma unroll
    for (int cp = 0; cp < 22; cp++) {
        float lo, hi;
        unpack2(accA2[cp], lo, hi);
        outA[2 * cp] = lo; outA[2 * cp + 1] = hi;
        unpack2(accB2[cp], lo, hi);
        outB[2 * cp] = lo; outB[2 * cp + 1] = hi;
    }
}

// ---------------- delta: softplus(dts @ dtw^T + bias), [B,K,L,DI] ----------------
#define DROWS 24
__global__ __launch_bounds__(384) void delta_kernel(const float* __restrict__ dtw,
                                                    const float* __restrict__ dtb)
{
    const int d = threadIdx.x;
    const int bk = blockIdx.y;
    const int k = bk & 3;
    const int row0 = bk * NL + blockIdx.x * DROWS;

    const float4* wp = (const float4*)(dtw + ((size_t)k * NDI + d) * NDTR);
    float4 w0 = __ldg(wp), w1 = __ldg(wp + 1), w2 = __ldg(wp + 2);
    const float bias = __ldg(dtb + k * NDI + d);

#pragma unroll 4
    for (int j = 0; j < DROWS; j++) {
        const int row = row0 + j;
        const float4* dq = (const float4*)(g_dbl + (size_t)row * NCC);
        float4 d0 = dq[0], d1 = dq[1], d2 = dq[2];
        float acc = bias;
        acc = fmaf(d0.x, w0.x, acc); acc = fmaf(d0.y, w0.y, acc);
        acc = fmaf(d0.z, w0.z, acc); acc = fmaf(d0.w, w0.w, acc);
        acc = fmaf(d1.x, w1.x, acc); acc = fmaf(d1.y, w1.y, acc);
        acc = fmaf(d1.z, w1.z, acc); acc = fmaf(d1.w, w1.w, acc);
        acc = fmaf(d2.x, w2.x, acc); acc = fmaf(d2.y, w2.y, acc);
        acc = fmaf(d2.z, w2.z, acc); acc = fmaf(d2.w, w2.w, acc);
        float sp = fmaxf(acc, 0.f) + __logf(1.f + __expf(-fabsf(acc)));
        g_delta[(size_t)row * NDI + d] = sp;
    }
}

// ---------------- selective scan: 4 threads per (b,k,d) lane, 4 states each ----------------
#define SCAN_UF 8
__global__ __launch_bounds__(192) void scan_kernel(const float* __restrict__ A_logs,
                                                   const float* __restrict__ Ds)
{
    const int lane = blockIdx.x * 48 + (threadIdx.x >> 2);
    const int t = threadIdx.x & 3;
    const int d = lane % NDI;
    const int bk = lane / NDI;
    const int k = bk & 3;

    const size_t bkL = (size_t)bk * NL;
    const float* __restrict__ dp = g_delta + bkL * NDI + d;
    const float* __restrict__ up = g_xs + bkL * NDI + d;
    const float* __restrict__ Bp = g_dbl + bkL * NCC + NDTR + t * 4;
    const float* __restrict__ Cp = Bp + NDS;
    float* __restrict__ yp = g_outy + bkL * NDI + d;

    const int ad = (k * NDI + d) * NDS + t * 4;
    const float A0 = -__expf(A_logs[ad + 0]);
    const float A1 = -__expf(A_logs[ad + 1]);
    const float A2 = -__expf(A_logs[ad + 2]);
    const float A3 = -__expf(A_logs[ad + 3]);
    const float Dv = Ds[k * NDI + d];

    const float dA1 = A1 - A0, dA2 = A2 - A1, dA3 = A3 - A2;
    const bool uni = (fabsf(dA2 - dA1) < 1e-4f) && (fabsf(dA3 - dA2) < 1e-4f);

    float s0 = 0.f, s1 = 0.f, s2 = 0.f, s3 = 0.f;
    if (uni) {
        for (int l0 = 0; l0 < NL; l0 += SCAN_UF) {
            float dl[SCAN_UF], ul[SCAN_UF];
            float4 Bv[SCAN_UF], Cv[SCAN_UF];
#pragma unroll
            for (int j = 0; j < SCAN_UF; j++) {
                dl[j] = dp[(size_t)(l0 + j) * NDI];
                ul[j] = up[(size_t)(l0 + j) * NDI];
                Bv[j] = *(const float4*)(Bp + (size_t)(l0 + j) * NCC);
                Cv[j] = *(const float4*)(Cp + (size_t)(l0 + j) * NCC);
            }
#pragma unroll
            for (int j = 0; j < SCAN_UF; j++) {
                float e0 = __expf(dl[j] * A0);
                float F  = __expf(dl[j] * dA1);
                float e1 = e0 * F;
                float e2 = e1 * F;
                float e3 = e2 * F;
                float du = dl[j] * ul[j];
                s0 = fmaf(s0, e0, du * Bv[j].x);
                s1 = fmaf(s1, e1, du * Bv[j].y);
                s2 = fmaf(s2, e2, du * Bv[j].z);
                s3 = fmaf(s3, e3, du * Bv[j].w);
                float p = fmaf(s0, Cv[j].x, fmaf(s1, Cv[j].y, fmaf(s2, Cv[j].z, s3 * Cv[j].w)));
                p += __shfl_xor_sync(0xffffffffu, p, 1);
                p += __shfl_xor_sync(0xffffffffu, p, 2);
                if (t == 0) yp[(size_t)(l0 + j) * NDI] = fmaf(Dv, ul[j], p);
            }
        }
    } else {
        for (int l0 = 0; l0 < NL; l0 += SCAN_UF) {
            float dl[SCAN_UF], ul[SCAN_UF];
            float4 Bv[SCAN_UF], Cv[SCAN_UF];
#pragma unroll
            for (int j = 0; j < SCAN_UF; j++) {
                dl[j] = dp[(size_t)(l0 + j) * NDI];
                ul[j] = up[(size_t)(l0 + j) * NDI];
                Bv[j] = *(const float4*)(Bp + (size_t)(l0 + j) * NCC);
                Cv[j] = *(const float4*)(Cp + (size_t)(l0 + j) * NCC);
            }
#pragma unroll
            for (int j = 0; j < SCAN_UF; j++) {
                float e0 = __expf(dl[j] * A0);
                float e1 = __expf(dl[j] * A1);
                float e2 = __expf(dl[j] * A2);
                float e3 = __expf(dl[j] * A3);
                float du = dl[j] * ul[j];
                s0 = fmaf(s0, e0, du * Bv[j].x);
                s1 = fmaf(s1, e1, du * Bv[j].y);
                s2 = fmaf(s2, e2, du * Bv[j].z);
                s3 = fmaf(s3, e3, du * Bv[j].w);
                float p = fmaf(s0, Cv[j].x, fmaf(s1, Cv[j].y, fmaf(s2, Cv[j].z, s3 * Cv[j].w)));
                p += __shfl_xor_sync(0xffffffffu, p, 1);
                p += __shfl_xor_sync(0xffffffffu, p, 2);
                if (t == 0) yp[(size_t)(l0 + j) * NDI] = fmaf(Dv, ul[j], p);
            }
        }
    }
}

// ---------------- combine 4 directions + LayerNorm + SiLU(z) gate ----------------
__global__ __launch_bounds__(384) void combine_kernel(const float* __restrict__ gam,
                                                      const float* __restrict__ bet)
{
    const int row = blockIdx.x;
    const int b = row / NL, l = row % NL;
    const int h = l / NW, w = l % NW;
    const int lT = w * NH + h;
    const int d = threadIdx.x;
    const float* oy = g_outy + (size_t)b * NK * NL * NDI;

    float v = oy[(size_t)(0 * NL + l) * NDI + d]
            + oy[(size_t)(2 * NL + (NL - 1 - l)) * NDI + d]
            + oy[(size_t)(1 * NL + lT) * NDI + d]
            + oy[(size_t)(3 * NL + (NL - 1 - lT)) * NDI + d];

    float sum = v, sq = v * v;
#pragma unroll
    for (int o = 16; o > 0; o >>= 1) {
        sum += __shfl_xor_sync(0xffffffffu, sum, o);
        sq  += __shfl_xor_sync(0xffffffffu, sq, o);
    }
    __shared__ float s1[12], s2[12];
    __shared__ float mu_s, rs_s;
    int wid = d >> 5, ln = d & 31;
    if (ln == 0) { s1[wid] = sum; s2[wid] = sq; }
    __syncthreads();
    if (d == 0) {
        float ts = 0.f, tq = 0.f;
#pragma unroll
        for (int i = 0; i < 12; i++) { ts += s1[i]; tq += s2[i]; }
        float mu = ts / (float)NDI;
        float var = tq / (float)NDI - mu * mu;
        mu_s = mu;
        rs_s = rsqrtf(var + 1e-5f);
    }
    __syncthreads();
    float yn = (v - mu_s) * rs_s * gam[d] + bet[d];
    float z = g_xz[(size_t)row * (2 * NDI) + NDI + d];
    g_xc[(size_t)row * NDI + d] = yn * silu_f(z);
}

// ---------------- launch ----------------
extern "C" void kernel_launch(void* const* d_in, const int* in_sizes, int n_in,
                              void* d_out, int out_size)
{
    const float* x         = (const float*)d_in[0];
    const float* xt        = (const float*)d_in[1];
    const float* in_proj_w = (const float*)d_in[2];
    const float* conv2d_w  = (const float*)d_in[3];
    const float* conv2d_b  = (const float*)d_in[4];
    const float* convxt_w  = (const float*)d_in[5];
    const float* convxt_b  = (const float*)d_in[6];
    const float* x_proj_w  = (const float*)d_in[7];
    const float* dtw       = (const float*)d_in[8];
    const float* dtb       = (const float*)d_in[9];
    const float* A_logs    = (const float*)d_in[10];
    const float* Dsv       = (const float*)d_in[11];
    const float* on_g      = (const float*)d_in[12];
    const float* on_b      = (const float*)d_in[13];
    const float* out_w     = (const float*)d_in[14];
    float* out = (float*)d_out;

    // 1) in_proj GEMM: [9216,192] x [768,192]^T -> g_xz [9216,768]
    gemm_inproj<<<dim3((2 * NDI) / 64, NBL / 128), 256>>>(x, in_proj_w);

    const int tot = NBL * NDI;
    const int nb = (tot + 255) / 256;
    // 2) depthwise conv + silu on xin -> g_xc
    conv_xc_kernel<<<nb, 256>>>(conv2d_w, conv2d_b);
    // 3) grouped conv + silu on xt -> g_xtc
    conv_xt_kernel<<<nb, 256>>>(xt, convxt_w, convxt_b);
    // 4) directional interleaved pooling -> g_xs [B,4,L,DI]
    interp_kernel<<<nb, 256>>>();
    // 5) x_dbl projection -> g_dbl [B,K,L,44]
    xdbl_kernel<<<dim3(NBL / 256, NK), 128>>>(x_proj_w);
    // 6) delta = softplus(dts @ dtw^T + bias) -> g_delta
    delta_kernel<<<dim3(NL / DROWS, NB * NK), 384>>>(dtw, dtb);
    // 7) selective scan -> g_outy [B,K,L,DI]
    scan_kernel<<<128, 192>>>(A_logs, Dsv);
    // 8) combine directions + LN + gate -> g_xc (reused as y)
    combine_kernel<<<NBL, 384>>>(on_g, on_b);
    // 9) out_proj GEMM: [9216,384] x [192,384]^T -> out [9216,192]
    gemm_outproj<<<dim3(NDM / 64, NBL / 128), 256>>>(out_w, out);
}

// round 17
// speedup vs baseline: 1.6662x; 1.6662x over previous
#include <cuda_runtime.h>
#include <math.h>
#include <stdint.h>

#define NB 4
#define NH 48
#define NW 48
#define NDM 192
#define NDI 384
#define NK 4
#define NL 2304
#define NDS 16
#define NDTR 12
#define NCC 44                 // DTR + 2*DS
#define NBL (NB*NL)            // 9216
#define NBKL (NB*NK*NL)        // 36864

// ---------------- scratch (static device memory; no allocations) ----------------
__device__ float g_xz[NBL * 2 * NDI];
__device__ float g_xc[NBL * NDI];            // aliased: becomes g_y after interp
__device__ float g_xtc[NBL * NDI];
__device__ float g_xs[NB * NK * NL * NDI];
__device__ float g_dbl[NBKL * NCC];
__device__ float g_delta[NB * NK * NL * NDI];
__device__ float g_outy[NB * NK * NL * NDI];

__device__ __forceinline__ float silu_f(float x) { return x / (1.f + __expf(-x)); }
__device__ __forceinline__ float mm2(float a, float b) { return 0.5f * (a + b) + fmaxf(a, b); }

// ---- packed fp32x2 helpers ----
__device__ __forceinline__ uint64_t pack2(float lo, float hi) {
    uint64_t r; asm("mov.b64 %0, {%1, %2};" : "=l"(r) : "f"(lo), "f"(hi)); return r;
}
__device__ __forceinline__ void unpack2(uint64_t v, float& lo, float& hi) {
    asm("mov.b64 {%0, %1}, %2;" : "=f"(lo), "=f"(hi) : "l"(v));
}
__device__ __forceinline__ void ffma2(uint64_t& d, uint64_t a, uint64_t b) {
    asm("fma.rn.f32x2 %0, %1, %2, %0;" : "+l"(d) : "l"(a), "l"(b));
}

// ---------------- generic SGEMM body: C[M,N] = A[M,K] * B[N,K]^T ----------------
// BM=128, BN=64, BK=16, 256 threads, 8x4 per-thread tile. Register-prefetch
// double buffering + FFMA2 packed accumulation. (R15-proven version; the R16
// duplicated-B layout hit 4-way STS bank conflicts — 544B row stride ≡ 0 mod 128.)
__device__ __forceinline__ void sgemm_body(const float* __restrict__ A,
                                           const float* __restrict__ B,
                                           float* __restrict__ C,
                                           int M, int N, int K)
{
    __shared__ float As[16][132];
    __shared__ float Bs[16][68];
    const int tid = threadIdx.x;
    const int row0 = blockIdx.y * 128;
    const int col0 = blockIdx.x * 64;
    const int tx = tid & 15;
    const int ty = tid >> 4;
    const int lr = tid >> 2;
    const int lc = (tid & 3) << 2;

    const float* Ap0 = A + (size_t)(row0 + lr) * K + lc;
    const float* Ap1 = A + (size_t)(row0 + lr + 64) * K + lc;
    const float* Bp0 = B + (size_t)(col0 + lr) * K + lc;

    uint64_t acc2[4][4];
#pragma unroll
    for (int i = 0; i < 4; i++)
#pragma unroll
        for (int j = 0; j < 4; j++) acc2[i][j] = 0ull;

    float4 a0 = *(const float4*)(Ap0);
    float4 a1 = *(const float4*)(Ap1);
    float4 b0 = *(const float4*)(Bp0);

    for (int k0 = 0; k0 < K; k0 += 16) {
        As[lc + 0][lr] = a0.x; As[lc + 1][lr] = a0.y; As[lc + 2][lr] = a0.z; As[lc + 3][lr] = a0.w;
        As[lc + 0][lr + 64] = a1.x; As[lc + 1][lr + 64] = a1.y; As[lc + 2][lr + 64] = a1.z; As[lc + 3][lr + 64] = a1.w;
        Bs[lc + 0][lr] = b0.x; Bs[lc + 1][lr] = b0.y; Bs[lc + 2][lr] = b0.z; Bs[lc + 3][lr] = b0.w;
        __syncthreads();
        if (k0 + 16 < K) {
            a0 = *(const float4*)(Ap0 + k0 + 16);
            a1 = *(const float4*)(Ap1 + k0 + 16);
            b0 = *(const float4*)(Bp0 + k0 + 16);
        }
#pragma unroll
        for (int kk = 0; kk < 16; kk++) {
            const float2* arow = (const float2*)&As[kk][ty * 8];
            float4 bv = *(const float4*)&Bs[kk][tx * 4];
            uint64_t bd[4];
            bd[0] = pack2(bv.x, bv.x); bd[1] = pack2(bv.y, bv.y);
            bd[2] = pack2(bv.z, bv.z); bd[3] = pack2(bv.w, bv.w);
#pragma unroll
            for (int ip = 0; ip < 4; ip++) {
                float2 af = arow[ip];
                uint64_t ap = pack2(af.x, af.y);
#pragma unroll
                for (int j = 0; j < 4; j++) ffma2(acc2[ip][j], ap, bd[j]);
            }
        }
        __syncthreads();
    }
#pragma unroll
    for (int ip = 0; ip < 4; ip++) {
        float lo[4], hi[4];
#pragma unroll
        for (int j = 0; j < 4; j++) unpack2(acc2[ip][j], lo[j], hi[j]);
        *(float4*)(C + (size_t)(row0 + ty * 8 + 2 * ip) * N + col0 + tx * 4) =
            make_float4(lo[0], lo[1], lo[2], lo[3]);
        *(float4*)(C + (size_t)(row0 + ty * 8 + 2 * ip + 1) * N + col0 + tx * 4) =
            make_float4(hi[0], hi[1], hi[2], hi[3]);
    }
}

__global__ __launch_bounds__(256) void gemm_inproj(const float* __restrict__ x,
                                                   const float* __restrict__ w)
{
    sgemm_body(x, w, g_xz, NBL, 2 * NDI, NDM);
}

__global__ __launch_bounds__(256) void gemm_outproj(const float* __restrict__ w,
                                                    float* __restrict__ out)
{
    sgemm_body(g_xc /* holds y after combine */, w, out, NBL, NDM, NDI);
}

// ---------------- depthwise conv on xin (from g_xz cols 0..383) + SiLU ----------------
__global__ void conv_xc_kernel(const float* __restrict__ wgt, const float* __restrict__ bias)
{
    int idx = blockIdx.x * blockDim.x + threadIdx.x;
    if (idx >= NBL * NDI) return;
    int c = idx % NDI;
    int pix = idx / NDI;
    int w = pix % NW;
    int h = (pix / NW) % NH;
    int b = pix / (NW * NH);
    float s = __ldg(bias + c);
#pragma unroll
    for (int dy = -1; dy <= 1; dy++) {
        int hh = h + dy;
        if (hh < 0 || hh >= NH) continue;
#pragma unroll
        for (int dx = -1; dx <= 1; dx++) {
            int ww = w + dx;
            if (ww < 0 || ww >= NW) continue;
            s = fmaf(g_xz[(size_t)(b * NL + hh * NW + ww) * (2 * NDI) + c],
                     __ldg(wgt + c * 9 + (dy + 1) * 3 + (dx + 1)), s);
        }
    }
    g_xc[(size_t)pix * NDI + c] = silu_f(s);
}

// ---------------- grouped conv on xt (192 in ch -> 384 out ch, ic = oc>>1) + SiLU ----------------
__global__ void conv_xt_kernel(const float* __restrict__ xt,
                               const float* __restrict__ wgt, const float* __restrict__ bias)
{
    int idx = blockIdx.x * blockDim.x + threadIdx.x;
    if (idx >= NBL * NDI) return;
    int c = idx % NDI;
    int pix = idx / NDI;
    int w = pix % NW;
    int h = (pix / NW) % NH;
    int b = pix / (NW * NH);
    int ic = c >> 1;
    float s = __ldg(bias + c);
#pragma unroll
    for (int dy = -1; dy <= 1; dy++) {
        int hh = h + dy;
        if (hh < 0 || hh >= NH) continue;
#pragma unroll
        for (int dx = -1; dx <= 1; dx++) {
            int ww = w + dx;
            if (ww < 0 || ww >= NW) continue;
            s = fmaf(__ldg(xt + (size_t)(b * NL + hh * NW + ww) * NDM + ic),
                     __ldg(wgt + c * 9 + (dy + 1) * 3 + (dx + 1)), s);
        }
    }
    g_xtc[(size_t)pix * NDI + c] = silu_f(s);
}

// ---------------- interpolate: build 4 directional sequences xs[b,k,l,d] ----------------
__global__ void interp_kernel()
{
    int idx = blockIdx.x * blockDim.x + threadIdx.x;
    if (idx >= NBL * NDI) return;
    int d = idx % NDI;
    int pix = idx / NDI;
    int w = pix % NW;
    int h = (pix / NW) % NH;
    int b = pix / (NW * NH);
    const float* XC = g_xc + (size_t)b * NL * NDI + d;
    const float* XT = g_xtc + (size_t)b * NL * NDI + d;

    float a0, a1;
    if ((h & 1) == 0) { a0 = XC[(h * NW + w) * NDI]; a1 = XC[((h + 1) * NW + w) * NDI]; }
    else              { a0 = XT[((h - 1) * NW + w) * NDI]; a1 = XT[(h * NW + w) * NDI]; }
    float vrow = mm2(a0, a1);
    if ((w & 1) == 0) { a0 = XC[(h * NW + w) * NDI]; a1 = XC[(h * NW + w + 1) * NDI]; }
    else              { a0 = XT[(h * NW + w - 1) * NDI]; a1 = XT[(h * NW + w) * NDI]; }
    float vcol = mm2(a0, a1);

    float* XS = g_xs + (size_t)b * NK * NL * NDI + d;
    int l0 = w * NH + h;
    XS[(size_t)(0 * NL + l0) * NDI] = vrow;
    XS[(size_t)(1 * NL + (w * NH + (NH - 1 - h))) * NDI] = vrow;
    int l2 = h * NW + w;
    XS[(size_t)(2 * NL + l2) * NDI] = vcol;
    XS[(size_t)(3 * NL + (h * NW + (NW - 1 - w))) * NDI] = vcol;
}

// ---------------- x_dbl: [44] = W_k[44,384] @ xs[b,k,l,:] ----------------
// w-pairs loaded directly as uint64 (LDS.64; same addresses as the float2 load,
// just no pack MOV).
__global__ __launch_bounds__(128) void xdbl_kernel(const float* __restrict__ Wp)
{
    __shared__ float xsm[256][33];
    __shared__ float ws2[32][48];
    const int kdir = blockIdx.y;
    const int row0 = blockIdx.x * 256;
    const int b = row0 / NL;
    const int l0 = row0 % NL;
    const float* xbase = g_xs + ((size_t)(b * NK + kdir) * NL + l0) * NDI;
    const int tid = threadIdx.x;

    uint64_t accA2[22], accB2[22];
#pragma unroll
    for (int c = 0; c < 22; c++) { accA2[c] = 0ull; accB2[c] = 0ull; }

    for (int dk0 = 0; dk0 < NDI; dk0 += 32) {
#pragma unroll
        for (int p = 0; p < 16; p++) {
            int lin = p * 128 + tid;
            int r = lin >> 3;
            int cc = (lin & 7) << 2;
            float4 v = *(const float4*)(xbase + (size_t)r * NDI + dk0 + cc);
            xsm[r][cc] = v.x; xsm[r][cc + 1] = v.y; xsm[r][cc + 2] = v.z; xsm[r][cc + 3] = v.w;
        }
        for (int p = tid; p < NCC * 32; p += 128) {
            int c = p >> 5, dd = p & 31;
            ws2[dd][c] = Wp[((size_t)kdir * NCC + c) * NDI + dk0 + dd];
        }
        __syncthreads();
        for (int kk = 0; kk < 32; kk++) {
            float xa = xsm[tid][kk];
            float xb = xsm[tid + 128][kk];
            uint64_t xad = pack2(xa, xa);
            uint64_t xbd = pack2(xb, xb);
            const uint64_t* wrow = (const uint64_t*)&ws2[kk][0];
#pragma unroll
            for (int cp = 0; cp < 22; cp++) {
                uint64_t wp2 = wrow[cp];
                ffma2(accA2[cp], xad, wp2);
                ffma2(accB2[cp], xbd, wp2);
            }
        }
        __syncthreads();
    }
    float* outA = g_dbl + ((size_t)(b * NK + kdir) * NL + l0 + tid) * NCC;
    float* outB = outA + (size_t)128 * NCC;
#pragma unroll
    for (int cp = 0; cp < 22; cp++) {
        float lo, hi;
        unpack2(accA2[cp], lo, hi);
        outA[2 * cp] = lo; outA[2 * cp + 1] = hi;
        unpack2(accB2[cp], lo, hi);
        outB[2 * cp] = lo; outB[2 * cp + 1] = hi;
    }
}

// ---------------- delta: softplus(dts @ dtw^T + bias), [B,K,L,DI] ----------------
#define DROWS 24
__global__ __launch_bounds__(384) void delta_kernel(const float* __restrict__ dtw,
                                                    const float* __restrict__ dtb)
{
    const int d = threadIdx.x;
    const int bk = blockIdx.y;
    const int k = bk & 3;
    const int row0 = bk * NL + blockIdx.x * DROWS;

    const float4* wp = (const float4*)(dtw + ((size_t)k * NDI + d) * NDTR);
    float4 w0 = __ldg(wp), w1 = __ldg(wp + 1), w2 = __ldg(wp + 2);
    const float bias = __ldg(dtb + k * NDI + d);

#pragma unroll 4
    for (int j = 0; j < DROWS; j++) {
        const int row = row0 + j;
        const float4* dq = (const float4*)(g_dbl + (size_t)row * NCC);
        float4 d0 = dq[0], d1 = dq[1], d2 = dq[2];
        float acc = bias;
        acc = fmaf(d0.x, w0.x, acc); acc = fmaf(d0.y, w0.y, acc);
        acc = fmaf(d0.z, w0.z, acc); acc = fmaf(d0.w, w0.w, acc);
        acc = fmaf(d1.x, w1.x, acc); acc = fmaf(d1.y, w1.y, acc);
        acc = fmaf(d1.z, w1.z, acc); acc = fmaf(d1.w, w1.w, acc);
        acc = fmaf(d2.x, w2.x, acc); acc = fmaf(d2.y, w2.y, acc);
        acc = fmaf(d2.z, w2.z, acc); acc = fmaf(d2.w, w2.w, acc);
        float sp = fmaxf(acc, 0.f) + __logf(1.f + __expf(-fabsf(acc)));
        g_delta[(size_t)row * NDI + d] = sp;
    }
}

// ---------------- selective scan: 4 threads per (b,k,d) lane, 4 states each ----------------
#define SCAN_UF 8
__global__ __launch_bounds__(192) void scan_kernel(const float* __restrict__ A_logs,
                                                   const float* __restrict__ Ds)
{
    const int lane = blockIdx.x * 48 + (threadIdx.x >> 2);
    const int t = threadIdx.x & 3;
    const int d = lane % NDI;
    const int bk = lane / NDI;
    const int k = bk & 3;

    const size_t bkL = (size_t)bk * NL;
    const float* __restrict__ dp = g_delta + bkL * NDI + d;
    const float* __restrict__ up = g_xs + bkL * NDI + d;
    const float* __restrict__ Bp = g_dbl + bkL * NCC + NDTR + t * 4;
    const float* __restrict__ Cp = Bp + NDS;
    float* __restrict__ yp = g_outy + bkL * NDI + d;

    const int ad = (k * NDI + d) * NDS + t * 4;
    const float A0 = -__expf(A_logs[ad + 0]);
    const float A1 = -__expf(A_logs[ad + 1]);
    const float A2 = -__expf(A_logs[ad + 2]);
    const float A3 = -__expf(A_logs[ad + 3]);
    const float Dv = Ds[k * NDI + d];

    const float dA1 = A1 - A0, dA2 = A2 - A1, dA3 = A3 - A2;
    const bool uni = (fabsf(dA2 - dA1) < 1e-4f) && (fabsf(dA3 - dA2) < 1e-4f);

    float s0 = 0.f, s1 = 0.f, s2 = 0.f, s3 = 0.f;
    if (uni) {
        for (int l0 = 0; l0 < NL; l0 += SCAN_UF) {
            float dl[SCAN_UF], ul[SCAN_UF];
            float4 Bv[SCAN_UF], Cv[SCAN_UF];
#pragma unroll
            for (int j = 0; j < SCAN_UF; j++) {
                dl[j] = dp[(size_t)(l0 + j) * NDI];
                ul[j] = up[(size_t)(l0 + j) * NDI];
                Bv[j] = *(const float4*)(Bp + (size_t)(l0 + j) * NCC);
                Cv[j] = *(const float4*)(Cp + (size_t)(l0 + j) * NCC);
            }
#pragma unroll
            for (int j = 0; j < SCAN_UF; j++) {
                float e0 = __expf(dl[j] * A0);
                float F  = __expf(dl[j] * dA1);
                float e1 = e0 * F;
                float e2 = e1 * F;
                float e3 = e2 * F;
                float du = dl[j] * ul[j];
                s0 = fmaf(s0, e0, du * Bv[j].x);
                s1 = fmaf(s1, e1, du * Bv[j].y);
                s2 = fmaf(s2, e2, du * Bv[j].z);
                s3 = fmaf(s3, e3, du * Bv[j].w);
                float p = fmaf(s0, Cv[j].x, fmaf(s1, Cv[j].y, fmaf(s2, Cv[j].z, s3 * Cv[j].w)));
                p += __shfl_xor_sync(0xffffffffu, p, 1);
                p += __shfl_xor_sync(0xffffffffu, p, 2);
                if (t == 0) yp[(size_t)(l0 + j) * NDI] = fmaf(Dv, ul[j], p);
            }
        }
    } else {
        for (int l0 = 0; l0 < NL; l0 += SCAN_UF) {
            float dl[SCAN_UF], ul[SCAN_UF];
            float4 Bv[SCAN_UF], Cv[SCAN_UF];
#pragma unroll
            for (int j = 0; j < SCAN_UF; j++) {
                dl[j] = dp[(size_t)(l0 + j) * NDI];
                ul[j] = up[(size_t)(l0 + j) * NDI];
                Bv[j] = *(const float4*)(Bp + (size_t)(l0 + j) * NCC);
                Cv[j] = *(const float4*)(Cp + (size_t)(l0 + j) * NCC);
            }
#pragma unroll
            for (int j = 0; j < SCAN_UF; j++) {
                float e0 = __expf(dl[j] * A0);
                float e1 = __expf(dl[j] * A1);
                float e2 = __expf(dl[j] * A2);
                float e3 = __expf(dl[j] * A3);
                float du = dl[j] * ul[j];
                s0 = fmaf(s0, e0, du * Bv[j].x);
                s1 = fmaf(s1, e1, du * Bv[j].y);
                s2 = fmaf(s2, e2, du * Bv[j].z);
                s3 = fmaf(s3, e3, du * Bv[j].w);
                float p = fmaf(s0, Cv[j].x, fmaf(s1, Cv[j].y, fmaf(s2, Cv[j].z, s3 * Cv[j].w)));
                p += __shfl_xor_sync(0xffffffffu, p, 1);
                p += __shfl_xor_sync(0xffffffffu, p, 2);
                if (t == 0) yp[(size_t)(l0 + j) * NDI] = fmaf(Dv, ul[j], p);
            }
        }
    }
}

// ---------------- combine 4 directions + LayerNorm + SiLU(z) gate ----------------
__global__ __launch_bounds__(384) void combine_kernel(const float* __restrict__ gam,
                                                      const float* __restrict__ bet)
{
    const int row = blockIdx.x;
    const int b = row / NL, l = row % NL;
    const int h = l / NW, w = l % NW;
    const int lT = w * NH + h;
    const int d = threadIdx.x;
    const float* oy = g_outy + (size_t)b * NK * NL * NDI;

    float v = oy[(size_t)(0 * NL + l) * NDI + d]
            + oy[(size_t)(2 * NL + (NL - 1 - l)) * NDI + d]
            + oy[(size_t)(1 * NL + lT) * NDI + d]
            + oy[(size_t)(3 * NL + (NL - 1 - lT)) * NDI + d];

    float sum = v, sq = v * v;
#pragma unroll
    for (int o = 16; o > 0; o >>= 1) {
        sum += __shfl_xor_sync(0xffffffffu, sum, o);
        sq  += __shfl_xor_sync(0xffffffffu, sq, o);
    }
    __shared__ float s1[12], s2[12];
    __shared__ float mu_s, rs_s;
    int wid = d >> 5, ln = d & 31;
    if (ln == 0) { s1[wid] = sum; s2[wid] = sq; }
    __syncthreads();
    if (d == 0) {
        float ts = 0.f, tq = 0.f;
#pragma unroll
        for (int i = 0; i < 12; i++) { ts += s1[i]; tq += s2[i]; }
        float mu = ts / (float)NDI;
        float var = tq / (float)NDI - mu * mu;
        mu_s = mu;
        rs_s = rsqrtf(var + 1e-5f);
    }
    __syncthreads();
    float yn = (v - mu_s) * rs_s * gam[d] + bet[d];
    float z = g_xz[(size_t)row * (2 * NDI) + NDI + d];
    g_xc[(size_t)row * NDI + d] = yn * silu_f(z);
}

// ---------------- launch ----------------
extern "C" void kernel_launch(void* const* d_in, const int* in_sizes, int n_in,
                              void* d_out, int out_size)
{
    const float* x         = (const float*)d_in[0];
    const float* xt        = (const float*)d_in[1];
    const float* in_proj_w = (const float*)d_in[2];
    const float* conv2d_w  = (const float*)d_in[3];
    const float* conv2d_b  = (const float*)d_in[4];
    const float* convxt_w  = (const float*)d_in[5];
    const float* convxt_b  = (const float*)d_in[6];
    const float* x_proj_w  = (const float*)d_in[7];
    const float* dtw       = (const float*)d_in[8];
    const float* dtb       = (const float*)d_in[9];
    const float* A_logs    = (const float*)d_in[10];
    const float* Dsv       = (const float*)d_in[11];
    const float* on_g      = (const float*)d_in[12];
    const float* on_b      = (const float*)d_in[13];
    const float* out_w     = (const float*)d_in[14];
    float* out = (float*)d_out;

    // 1) in_proj GEMM: [9216,192] x [768,192]^T -> g_xz [9216,768]
    gemm_inproj<<<dim3((2 * NDI) / 64, NBL / 128), 256>>>(x, in_proj_w);

    const int tot = NBL * NDI;
    const int nb = (tot + 255) / 256;
    // 2) depthwise conv + silu on xin -> g_xc
    conv_xc_kernel<<<nb, 256>>>(conv2d_w, conv2d_b);
    // 3) grouped conv + silu on xt -> g_xtc
    conv_xt_kernel<<<nb, 256>>>(xt, convxt_w, convxt_b);
    // 4) directional interleaved pooling -> g_xs [B,4,L,DI]
    interp_kernel<<<nb, 256>>>();
    // 5) x_dbl projection -> g_dbl [B,K,L,44]
    xdbl_kernel<<<dim3(NBL / 256, NK), 128>>>(x_proj_w);
    // 6) delta = softplus(dts @ dtw^T + bias) -> g_delta
    delta_kernel<<<dim3(NL / DROWS, NB * NK), 384>>>(dtw, dtb);
    // 7) selective scan -> g_outy [B,K,L,DI]
    scan_kernel<<<128, 192>>>(A_logs, Dsv);
    // 8) combine directions + LN + gate -> g_xc (reused as y)
    combine_kernel<<<NBL, 384>>>(on_g, on_b);
    // 9) out_proj GEMM: [9216,384] x [192,384]^T -> out [9216,192]
    gemm_outproj<<<dim3(NDM / 64, NBL / 128), 256>>>(out_w, out);
}